// round 1
// baseline (speedup 1.0000x reference)
#include <cuda_runtime.h>
#include <math.h>

// ---------------- problem constants ----------------
#define NN_AG 2048      // agents
#define HID   2048      // hidden
#define OBS_D 1024
#define ACT_D 64
#define ITERS 3

// ---------------- device scratch (no allocs allowed) ----------------
__device__ float g_e   [NN_AG * HID];
__device__ float g_h   [NN_AG * HID];
__device__ float g_cell[NN_AG * HID];
__device__ float g_inp [NN_AG * HID];
__device__ float g_Gt  [NN_AG * NN_AG];
__device__ float g_z   [(size_t)NN_AG * 4 * HID];   // also reused as gate-logit scratch
__device__ float g_bsum[4 * HID];
__device__ float g_nalive;

__device__ __forceinline__ float sigmoidf_(float x) {
    return 1.0f / (1.0f + expf(-x));
}

// ---------------- SGEMM 128x128x8, 256 threads, 8x8 per thread ----------------
// C[M,N] = A[M,K] * op(B) (+bias per-col) (+=C if ACCUM) (tanh if ACT==1)
// TB=true : B is [N,K] row-major (NT gemm, C = A * B^T)
// TB=false: B is [K,N] row-major (NN gemm)
// Requires: M%128==0, N%128==0, K%8==0.
template<bool TB, bool ACCUM, int ACT>
__global__ __launch_bounds__(256)
void sgemm_k(const float* __restrict__ A, const float* __restrict__ B,
             const float* __restrict__ bias, float* __restrict__ C,
             int M, int N, int K)
{
    __shared__ float As[8][128];
    __shared__ float Bs[8][128];

    const int tid = threadIdx.x;
    const int m0 = blockIdx.y * 128;
    const int n0 = blockIdx.x * 128;

    const int trow = tid >> 4;          // 0..15
    const int tcol = tid & 15;          // 0..15

    float acc[8][8];
#pragma unroll
    for (int i = 0; i < 8; i++)
#pragma unroll
        for (int j = 0; j < 8; j++) acc[i][j] = 0.0f;

    const int arow = tid >> 1;          // 0..127
    const int acol = (tid & 1) * 4;     // 0 or 4

    for (int k0 = 0; k0 < K; k0 += 8) {
        // load A tile (transposed store into As[k][m])
        float4 av = *(const float4*)(A + (size_t)(m0 + arow) * K + k0 + acol);
        As[acol + 0][arow] = av.x;
        As[acol + 1][arow] = av.y;
        As[acol + 2][arow] = av.z;
        As[acol + 3][arow] = av.w;

        if (TB) {
            float4 bv = *(const float4*)(B + (size_t)(n0 + arow) * K + k0 + acol);
            Bs[acol + 0][arow] = bv.x;
            Bs[acol + 1][arow] = bv.y;
            Bs[acol + 2][arow] = bv.z;
            Bs[acol + 3][arow] = bv.w;
        } else {
            const int brow = tid >> 5;            // 0..7
            const int bcol = (tid & 31) * 4;      // 0..124
            float4 bv = *(const float4*)(B + (size_t)(k0 + brow) * N + n0 + bcol);
            *(float4*)&Bs[brow][bcol] = bv;
        }
        __syncthreads();

#pragma unroll
        for (int k = 0; k < 8; k++) {
            float a[8], b[8];
            *(float4*)(a)     = *(const float4*)&As[k][trow * 8];
            *(float4*)(a + 4) = *(const float4*)&As[k][trow * 8 + 4];
            *(float4*)(b)     = *(const float4*)&Bs[k][tcol * 8];
            *(float4*)(b + 4) = *(const float4*)&Bs[k][tcol * 8 + 4];
#pragma unroll
            for (int i = 0; i < 8; i++)
#pragma unroll
                for (int j = 0; j < 8; j++)
                    acc[i][j] = fmaf(a[i], b[j], acc[i][j]);
        }
        __syncthreads();
    }

#pragma unroll
    for (int i = 0; i < 8; i++) {
        const int gm = m0 + trow * 8 + i;
#pragma unroll
        for (int j = 0; j < 8; j++) {
            const int gn = n0 + tcol * 8 + j;
            float v = acc[i][j];
            if (bias) v += bias[gn];
            size_t idx = (size_t)gm * N + gn;
            if (ACCUM) v += C[idx];
            if (ACT == 1) v = tanhf(v);
            C[idx] = v;
        }
    }
}

// ---------------- n_alive reduction ----------------
__global__ void nalive_k(const float* __restrict__ alive, float* __restrict__ out, int n)
{
    __shared__ float s[256];
    float v = 0.0f;
    for (int i = threadIdx.x; i < n; i += 256) v += alive[i];
    s[threadIdx.x] = v;
    __syncthreads();
    for (int st = 128; st > 0; st >>= 1) {
        if (threadIdx.x < st) s[threadIdx.x] += s[threadIdx.x + st];
        __syncthreads();
    }
    if (threadIdx.x == 0) *out = s[0];
}

// ---------------- bias sum ----------------
__global__ void bias_sum_k(const float* __restrict__ a, const float* __restrict__ b,
                           float* __restrict__ o, int n)
{
    int i = blockIdx.x * blockDim.x + threadIdx.x;
    if (i < n) o[i] = a[i] + b[i];
}

// ---------------- gate transpose: Gt[i,j] = ceil(sigmoid(L[j,i])) * static_w[j,i] ----
__global__ void gate_tr_k(const float* __restrict__ L, const float* __restrict__ alive,
                          const float* __restrict__ nalive, float* __restrict__ Gt, int n)
{
    __shared__ float tile[32][33];
    const int j0 = blockIdx.x * 32;
    const int i0 = blockIdx.y * 32;
    const int x = threadIdx.x;      // 0..31
    const int y = threadIdx.y;      // 0..7

#pragma unroll
    for (int dy = 0; dy < 32; dy += 8)
        tile[y + dy][x] = L[(size_t)(j0 + y + dy) * n + i0 + x];
    __syncthreads();

    const float inv = 1.0f / (*nalive - 1.0f);
#pragma unroll
    for (int dy = 0; dy < 32; dy += 8) {
        const int i = i0 + y + dy;     // output row
        const int j = j0 + x;          // output col
        float lg = tile[x][y + dy];    // = L[j, i]
        float gate = ceilf(1.0f / (1.0f + expf(-lg)));
        float sw = (i == j) ? 0.0f : alive[i] * alive[j] * inv;
        Gt[(size_t)i * n + j] = gate * sw;
    }
}

// ---------------- LSTM cell update ----------------
__global__ void lstm_k(const float* __restrict__ z, float* __restrict__ cell,
                       float* __restrict__ h)
{
    int idx = blockIdx.x * blockDim.x + threadIdx.x;
    if (idx >= NN_AG * HID) return;
    int row = idx / HID, col = idx % HID;
    const float* zr = z + (size_t)row * 4 * HID;
    float zi = zr[col];
    float zf = zr[HID + col];
    float zg = zr[2 * HID + col];
    float zo = zr[3 * HID + col];
    float c = sigmoidf_(zf) * cell[idx] + sigmoidf_(zi) * tanhf(zg);
    cell[idx] = c;
    h[idx] = sigmoidf_(zo) * tanhf(c);
}

// ---------------- head: logits + log_softmax + value, one block per agent ----------
__global__ __launch_bounds__(256)
void head_k(const float* __restrict__ h,
            const float* __restrict__ act_w, const float* __restrict__ act_b,
            const float* __restrict__ val_w, const float* __restrict__ val_b,
            float* __restrict__ out)
{
    const int n = blockIdx.x;
    const int tid = threadIdx.x;
    __shared__ float sh[HID];
    __shared__ float partial[4][ACT_D];
    __shared__ float vred[256];
    __shared__ float logits[ACT_D];

    const float* hr = h + (size_t)n * HID;
    for (int k = tid; k < HID; k += 256) sh[k] = hr[k];
    __syncthreads();

    const int col = tid & 63;
    const int part = tid >> 6;
    const float* w = act_w + (size_t)col * HID;
    float s = 0.0f;
    const int kbeg = part * (HID / 4);
    for (int k = kbeg; k < kbeg + HID / 4; k++) s = fmaf(sh[k], w[k], s);
    partial[part][col] = s;

    float v = 0.0f;
    for (int k = tid; k < HID; k += 256) v = fmaf(sh[k], val_w[k], v);
    vred[tid] = v;
    __syncthreads();

    if (tid < ACT_D)
        logits[tid] = partial[0][tid] + partial[1][tid] + partial[2][tid]
                    + partial[3][tid] + act_b[tid];

    for (int st = 128; st > 0; st >>= 1) {
        if (tid < st) vred[tid] += vred[tid + st];
        __syncthreads();
    }
    if (tid == 0) out[(size_t)NN_AG * ACT_D + n] = vred[0] + val_b[0];

    // log_softmax over 64 logits on warp 0
    if (tid < 32) {
        float a = logits[tid], b = logits[tid + 32];
        float m = fmaxf(a, b);
#pragma unroll
        for (int o = 16; o > 0; o >>= 1) m = fmaxf(m, __shfl_xor_sync(0xffffffffu, m, o));
        float se = expf(a - m) + expf(b - m);
#pragma unroll
        for (int o = 16; o > 0; o >>= 1) se += __shfl_xor_sync(0xffffffffu, se, o);
        float lse = m + logf(se);
        out[(size_t)n * ACT_D + tid]      = a - lse;
        out[(size_t)n * ACT_D + tid + 32] = b - lse;
    }
}

// ---------------- launcher ----------------
extern "C" void kernel_launch(void* const* d_in, const int* in_sizes, int n_in,
                              void* d_out, int out_size)
{
    const float* obs    = (const float*)d_in[0];
    const float* alive  = (const float*)d_in[1];
    const float* enc_w  = (const float*)d_in[2];
    const float* enc_b  = (const float*)d_in[3];
    const float* gw     = (const float*)d_in[4];
    const float* gb     = (const float*)d_in[5];
    const float* w_ih   = (const float*)d_in[6];
    const float* w_hh   = (const float*)d_in[7];
    const float* b_ih   = (const float*)d_in[8];
    const float* b_hh   = (const float*)d_in[9];
    const float* act_w  = (const float*)d_in[10];
    const float* act_b  = (const float*)d_in[11];
    const float* val_w  = (const float*)d_in[12];
    const float* val_b  = (const float*)d_in[13];
    float* out = (float*)d_out;

    float *e, *h, *cell, *inp, *Gt, *z, *bsum, *nal;
    cudaGetSymbolAddress((void**)&e,    g_e);
    cudaGetSymbolAddress((void**)&h,    g_h);
    cudaGetSymbolAddress((void**)&cell, g_cell);
    cudaGetSymbolAddress((void**)&inp,  g_inp);
    cudaGetSymbolAddress((void**)&Gt,   g_Gt);
    cudaGetSymbolAddress((void**)&z,    g_z);
    cudaGetSymbolAddress((void**)&bsum, g_bsum);
    cudaGetSymbolAddress((void**)&nal,  g_nalive);

    const size_t NH = (size_t)NN_AG * HID;

    // state init (must be per-call: deterministic, graph-replayable)
    cudaMemsetAsync(h,    0, NH * sizeof(float));
    cudaMemsetAsync(cell, 0, NH * sizeof(float));

    nalive_k<<<1, 256>>>(alive, nal, NN_AG);
    bias_sum_k<<<(4 * HID + 255) / 256, 256>>>(b_ih, b_hh, bsum, 4 * HID);

    // encoder: e = tanh(obs @ enc_w^T + enc_b)   [2048 x 2048, K=1024]
    {
        dim3 grid(HID / 128, NN_AG / 128);
        sgemm_k<true, false, 1><<<grid, 256>>>(obs, enc_w, enc_b, e,
                                               NN_AG, HID, OBS_D);
    }

    const dim3 gridNN(NN_AG / 128, NN_AG / 128);   // 2048x2048
    const dim3 gridZ(4 * HID / 128, NN_AG / 128);  // 2048x8192
    const dim3 gridTr(NN_AG / 32, NN_AG / 32);
    const dim3 blkTr(32, 8);

    for (int it = 0; it < ITERS; it++) {
        if (it > 0) {
            // gate logits into z-scratch: L = h @ g_w^T + g_b
            sgemm_k<true, false, 0><<<gridNN, 256>>>(h, gw, gb, z,
                                                     NN_AG, NN_AG, HID);
            // Gt[i,j] = ceil(sigmoid(L[j,i])) * static_w[j,i]
            gate_tr_k<<<gridTr, blkTr>>>(z, alive, nal, Gt, NN_AG);
            // inp = e + Gt @ h
            cudaMemcpyAsync(inp, e, NH * sizeof(float), cudaMemcpyDeviceToDevice);
            sgemm_k<false, true, 0><<<gridNN, 256>>>(Gt, h, (const float*)nullptr,
                                                     inp, NN_AG, NN_AG, HID);
        } else {
            // iter 0: c == 0 exactly -> inp = e (gate GEMM provably unused)
            cudaMemcpyAsync(inp, e, NH * sizeof(float), cudaMemcpyDeviceToDevice);
        }

        // z = inp @ w_ih^T + (b_ih + b_hh)
        sgemm_k<true, false, 0><<<gridZ, 256>>>(inp, w_ih, bsum, z,
                                                NN_AG, 4 * HID, HID);
        if (it > 0) {
            // z += h @ w_hh^T   (h==0 at iter 0 -> exact skip)
            sgemm_k<true, true, 0><<<gridZ, 256>>>(h, w_hh, (const float*)nullptr,
                                                   z, NN_AG, 4 * HID, HID);
        }

        lstm_k<<<(int)((NH + 255) / 256), 256>>>(z, cell, h);
    }

    head_k<<<NN_AG, 256>>>(h, act_w, act_b, val_w, val_b, out);
}

// round 2
// speedup vs baseline: 1.0016x; 1.0016x over previous
#include <cuda_runtime.h>
#include <math.h>

// ---------------- problem constants ----------------
#define NN_AG 2048      // agents
#define HID   2048      // hidden
#define OBS_D 1024
#define ACT_D 64
#define ITERS 3

// ---------------- device scratch (no allocs allowed) ----------------
__device__ float g_e   [NN_AG * HID];
__device__ float g_h   [NN_AG * HID];
__device__ float g_cell[NN_AG * HID];
__device__ float g_inp [NN_AG * HID];
__device__ float g_Gt  [NN_AG * NN_AG];
__device__ float g_z   [(size_t)NN_AG * 4 * HID];   // also reused as gate-logit scratch
__device__ float g_bsum[4 * HID];
__device__ float g_nalive;

__device__ __forceinline__ float sigmoidf_(float x) {
    return 1.0f / (1.0f + expf(-x));
}

// ---------------- SGEMM 128x128x8, 256 threads, 8x8 per thread ----------------
// C[M,N] = A[M,K] * op(B) (+bias per-col) (+=C if ACCUM) (tanh if ACT==1)
// TB=true : B is [N,K] row-major (NT gemm, C = A * B^T)
// TB=false: B is [K,N] row-major (NN gemm)
// Requires: M%128==0, N%128==0, K%8==0.
template<bool TB, bool ACCUM, int ACT>
__global__ __launch_bounds__(256)
void sgemm_k(const float* __restrict__ A, const float* __restrict__ B,
             const float* __restrict__ bias, float* __restrict__ C,
             int M, int N, int K)
{
    __shared__ float As[8][128];
    __shared__ float Bs[8][128];

    const int tid = threadIdx.x;
    const int m0 = blockIdx.y * 128;
    const int n0 = blockIdx.x * 128;

    const int trow = tid >> 4;          // 0..15
    const int tcol = tid & 15;          // 0..15

    float acc[8][8];
#pragma unroll
    for (int i = 0; i < 8; i++)
#pragma unroll
        for (int j = 0; j < 8; j++) acc[i][j] = 0.0f;

    const int arow = tid >> 1;          // 0..127
    const int acol = (tid & 1) * 4;     // 0 or 4

    for (int k0 = 0; k0 < K; k0 += 8) {
        // load A tile (transposed store into As[k][m])
        float4 av = *(const float4*)(A + (size_t)(m0 + arow) * K + k0 + acol);
        As[acol + 0][arow] = av.x;
        As[acol + 1][arow] = av.y;
        As[acol + 2][arow] = av.z;
        As[acol + 3][arow] = av.w;

        if (TB) {
            float4 bv = *(const float4*)(B + (size_t)(n0 + arow) * K + k0 + acol);
            Bs[acol + 0][arow] = bv.x;
            Bs[acol + 1][arow] = bv.y;
            Bs[acol + 2][arow] = bv.z;
            Bs[acol + 3][arow] = bv.w;
        } else {
            const int brow = tid >> 5;            // 0..7
            const int bcol = (tid & 31) * 4;      // 0..124
            float4 bv = *(const float4*)(B + (size_t)(k0 + brow) * N + n0 + bcol);
            *(float4*)&Bs[brow][bcol] = bv;
        }
        __syncthreads();

#pragma unroll
        for (int k = 0; k < 8; k++) {
            float a[8], b[8];
            *(float4*)(a)     = *(const float4*)&As[k][trow * 8];
            *(float4*)(a + 4) = *(const float4*)&As[k][trow * 8 + 4];
            *(float4*)(b)     = *(const float4*)&Bs[k][tcol * 8];
            *(float4*)(b + 4) = *(const float4*)&Bs[k][tcol * 8 + 4];
#pragma unroll
            for (int i = 0; i < 8; i++)
#pragma unroll
                for (int j = 0; j < 8; j++)
                    acc[i][j] = fmaf(a[i], b[j], acc[i][j]);
        }
        __syncthreads();
    }

#pragma unroll
    for (int i = 0; i < 8; i++) {
        const int gm = m0 + trow * 8 + i;
#pragma unroll
        for (int j = 0; j < 8; j++) {
            const int gn = n0 + tcol * 8 + j;
            float v = acc[i][j];
            if (bias) v += bias[gn];
            size_t idx = (size_t)gm * N + gn;
            if (ACCUM) v += C[idx];
            if (ACT == 1) v = tanhf(v);
            C[idx] = v;
        }
    }
}

// ---------------- n_alive reduction ----------------
__global__ void nalive_k(const float* __restrict__ alive, float* __restrict__ out, int n)
{
    __shared__ float s[256];
    float v = 0.0f;
    for (int i = threadIdx.x; i < n; i += 256) v += alive[i];
    s[threadIdx.x] = v;
    __syncthreads();
    for (int st = 128; st > 0; st >>= 1) {
        if (threadIdx.x < st) s[threadIdx.x] += s[threadIdx.x + st];
        __syncthreads();
    }
    if (threadIdx.x == 0) *out = s[0];
}

// ---------------- bias sum ----------------
__global__ void bias_sum_k(const float* __restrict__ a, const float* __restrict__ b,
                           float* __restrict__ o, int n)
{
    int i = blockIdx.x * blockDim.x + threadIdx.x;
    if (i < n) o[i] = a[i] + b[i];
}

// ---------------- gate transpose: Gt[i,j] = ceil(sigmoid(L[j,i])) * static_w[j,i] ----
__global__ void gate_tr_k(const float* __restrict__ L, const float* __restrict__ alive,
                          const float* __restrict__ nalive, float* __restrict__ Gt, int n)
{
    __shared__ float tile[32][33];
    const int j0 = blockIdx.x * 32;
    const int i0 = blockIdx.y * 32;
    const int x = threadIdx.x;      // 0..31
    const int y = threadIdx.y;      // 0..7

#pragma unroll
    for (int dy = 0; dy < 32; dy += 8)
        tile[y + dy][x] = L[(size_t)(j0 + y + dy) * n + i0 + x];
    __syncthreads();

    const float inv = 1.0f / (*nalive - 1.0f);
#pragma unroll
    for (int dy = 0; dy < 32; dy += 8) {
        const int i = i0 + y + dy;     // output row
        const int j = j0 + x;          // output col
        float lg = tile[x][y + dy];    // = L[j, i]
        float gate = ceilf(1.0f / (1.0f + expf(-lg)));
        float sw = (i == j) ? 0.0f : alive[i] * alive[j] * inv;
        Gt[(size_t)i * n + j] = gate * sw;
    }
}

// ---------------- LSTM cell update ----------------
__global__ void lstm_k(const float* __restrict__ z, float* __restrict__ cell,
                       float* __restrict__ h)
{
    int idx = blockIdx.x * blockDim.x + threadIdx.x;
    if (idx >= NN_AG * HID) return;
    int row = idx / HID, col = idx % HID;
    const float* zr = z + (size_t)row * 4 * HID;
    float zi = zr[col];
    float zf = zr[HID + col];
    float zg = zr[2 * HID + col];
    float zo = zr[3 * HID + col];
    float c = sigmoidf_(zf) * cell[idx] + sigmoidf_(zi) * tanhf(zg);
    cell[idx] = c;
    h[idx] = sigmoidf_(zo) * tanhf(c);
}

// ---------------- head: logits + log_softmax + value, one block per agent ----------
__global__ __launch_bounds__(256)
void head_k(const float* __restrict__ h,
            const float* __restrict__ act_w, const float* __restrict__ act_b,
            const float* __restrict__ val_w, const float* __restrict__ val_b,
            float* __restrict__ out)
{
    const int n = blockIdx.x;
    const int tid = threadIdx.x;
    __shared__ float sh[HID];
    __shared__ float partial[4][ACT_D];
    __shared__ float vred[256];
    __shared__ float logits[ACT_D];

    const float* hr = h + (size_t)n * HID;
    for (int k = tid; k < HID; k += 256) sh[k] = hr[k];
    __syncthreads();

    const int col = tid & 63;
    const int part = tid >> 6;
    const float* w = act_w + (size_t)col * HID;
    float s = 0.0f;
    const int kbeg = part * (HID / 4);
    for (int k = kbeg; k < kbeg + HID / 4; k++) s = fmaf(sh[k], w[k], s);
    partial[part][col] = s;

    float v = 0.0f;
    for (int k = tid; k < HID; k += 256) v = fmaf(sh[k], val_w[k], v);
    vred[tid] = v;
    __syncthreads();

    if (tid < ACT_D)
        logits[tid] = partial[0][tid] + partial[1][tid] + partial[2][tid]
                    + partial[3][tid] + act_b[tid];

    for (int st = 128; st > 0; st >>= 1) {
        if (tid < st) vred[tid] += vred[tid + st];
        __syncthreads();
    }
    if (tid == 0) out[(size_t)NN_AG * ACT_D + n] = vred[0] + val_b[0];

    // log_softmax over 64 logits on warp 0
    if (tid < 32) {
        float a = logits[tid], b = logits[tid + 32];
        float m = fmaxf(a, b);
#pragma unroll
        for (int o = 16; o > 0; o >>= 1) m = fmaxf(m, __shfl_xor_sync(0xffffffffu, m, o));
        float se = expf(a - m) + expf(b - m);
#pragma unroll
        for (int o = 16; o > 0; o >>= 1) se += __shfl_xor_sync(0xffffffffu, se, o);
        float lse = m + logf(se);
        out[(size_t)n * ACT_D + tid]      = a - lse;
        out[(size_t)n * ACT_D + tid + 32] = b - lse;
    }
}

// ---------------- launcher ----------------
extern "C" void kernel_launch(void* const* d_in, const int* in_sizes, int n_in,
                              void* d_out, int out_size)
{
    const float* obs    = (const float*)d_in[0];
    const float* alive  = (const float*)d_in[1];
    const float* enc_w  = (const float*)d_in[2];
    const float* enc_b  = (const float*)d_in[3];
    const float* gw     = (const float*)d_in[4];
    const float* gb     = (const float*)d_in[5];
    const float* w_ih   = (const float*)d_in[6];
    const float* w_hh   = (const float*)d_in[7];
    const float* b_ih   = (const float*)d_in[8];
    const float* b_hh   = (const float*)d_in[9];
    const float* act_w  = (const float*)d_in[10];
    const float* act_b  = (const float*)d_in[11];
    const float* val_w  = (const float*)d_in[12];
    const float* val_b  = (const float*)d_in[13];
    float* out = (float*)d_out;

    float *e, *h, *cell, *inp, *Gt, *z, *bsum, *nal;
    cudaGetSymbolAddress((void**)&e,    g_e);
    cudaGetSymbolAddress((void**)&h,    g_h);
    cudaGetSymbolAddress((void**)&cell, g_cell);
    cudaGetSymbolAddress((void**)&inp,  g_inp);
    cudaGetSymbolAddress((void**)&Gt,   g_Gt);
    cudaGetSymbolAddress((void**)&z,    g_z);
    cudaGetSymbolAddress((void**)&bsum, g_bsum);
    cudaGetSymbolAddress((void**)&nal,  g_nalive);

    const size_t NH = (size_t)NN_AG * HID;

    // state init (must be per-call: deterministic, graph-replayable)
    cudaMemsetAsync(h,    0, NH * sizeof(float));
    cudaMemsetAsync(cell, 0, NH * sizeof(float));

    nalive_k<<<1, 256>>>(alive, nal, NN_AG);
    bias_sum_k<<<(4 * HID + 255) / 256, 256>>>(b_ih, b_hh, bsum, 4 * HID);

    // encoder: e = tanh(obs @ enc_w^T + enc_b)   [2048 x 2048, K=1024]
    {
        dim3 grid(HID / 128, NN_AG / 128);
        sgemm_k<true, false, 1><<<grid, 256>>>(obs, enc_w, enc_b, e,
                                               NN_AG, HID, OBS_D);
    }

    const dim3 gridNN(NN_AG / 128, NN_AG / 128);   // 2048x2048
    const dim3 gridZ(4 * HID / 128, NN_AG / 128);  // 2048x8192
    const dim3 gridTr(NN_AG / 32, NN_AG / 32);
    const dim3 blkTr(32, 8);

    for (int it = 0; it < ITERS; it++) {
        if (it > 0) {
            // gate logits into z-scratch: L = h @ g_w^T + g_b
            sgemm_k<true, false, 0><<<gridNN, 256>>>(h, gw, gb, z,
                                                     NN_AG, NN_AG, HID);
            // Gt[i,j] = ceil(sigmoid(L[j,i])) * static_w[j,i]
            gate_tr_k<<<gridTr, blkTr>>>(z, alive, nal, Gt, NN_AG);
            // inp = e + Gt @ h
            cudaMemcpyAsync(inp, e, NH * sizeof(float), cudaMemcpyDeviceToDevice);
            sgemm_k<false, true, 0><<<gridNN, 256>>>(Gt, h, (const float*)nullptr,
                                                     inp, NN_AG, NN_AG, HID);
        } else {
            // iter 0: c == 0 exactly -> inp = e (gate GEMM provably unused)
            cudaMemcpyAsync(inp, e, NH * sizeof(float), cudaMemcpyDeviceToDevice);
        }

        // z = inp @ w_ih^T + (b_ih + b_hh)
        sgemm_k<true, false, 0><<<gridZ, 256>>>(inp, w_ih, bsum, z,
                                                NN_AG, 4 * HID, HID);
        if (it > 0) {
            // z += h @ w_hh^T   (h==0 at iter 0 -> exact skip)
            sgemm_k<true, true, 0><<<gridZ, 256>>>(h, w_hh, (const float*)nullptr,
                                                   z, NN_AG, 4 * HID, HID);
        }

        lstm_k<<<(int)((NH + 255) / 256), 256>>>(z, cell, h);
    }

    head_k<<<NN_AG, 256>>>(h, act_w, act_b, val_w, val_b, out);
}

// round 5
// speedup vs baseline: 3.5485x; 3.5430x over previous
#include <cuda_runtime.h>
#include <cuda_bf16.h>
#include <math.h>
#include <stdint.h>

// ---------------- problem constants ----------------
#define NN_AG 2048
#define HID   2048
#define OBS_D 1024
#define ACT_D 64
#define ITERS 3

// ---------------- device scratch (no allocs allowed) ----------------
// fragment-major packed bf16 operands; one 8KB block = 128 rows x 32 k
__device__ __align__(16) __nv_bfloat16 g_Apack[(size_t)2 * 16 * 128 * 4096]; // [inp|h] rows
__device__ __align__(16) __nv_bfloat16 g_Aobs [(size_t)2 * 16 * 32  * 4096];
__device__ __align__(16) __nv_bfloat16 g_Wcat [(size_t)2 * 64 * 128 * 4096]; // [w_ih|w_hh]
__device__ __align__(16) __nv_bfloat16 g_Wenc [(size_t)2 * 16 * 32  * 4096];
__device__ float g_e   [(size_t)NN_AG * HID];
__device__ float g_h   [(size_t)NN_AG * HID];
__device__ float g_cell[(size_t)NN_AG * HID];
__device__ float g_inp [(size_t)NN_AG * HID];
__device__ float g_z   [(size_t)NN_AG * 4 * HID];
__device__ float g_part[16 * HID];
__device__ float g_S   [HID];
__device__ float g_bsum[4 * HID];
__device__ float g_nalive;

__device__ __forceinline__ float sigf(float x) { return 1.0f / (1.0f + expf(-x)); }

// ---------------- low-level helpers ----------------
__device__ __forceinline__ uint32_t smem_u32(const void* p) {
    uint32_t a;
    asm("{ .reg .u64 t; cvta.to.shared.u64 t, %1; cvt.u32.u64 %0, t; }" : "=r"(a) : "l"(p));
    return a;
}
__device__ __forceinline__ void cpasync16(uint32_t d, const void* s) {
    asm volatile("cp.async.cg.shared.global [%0], [%1], 16;" :: "r"(d), "l"(s));
}
__device__ __forceinline__ uint4 lds128(uint32_t a) {
    uint4 v;
    asm volatile("ld.shared.v4.b32 {%0,%1,%2,%3}, [%4];"
                 : "=r"(v.x), "=r"(v.y), "=r"(v.z), "=r"(v.w) : "r"(a));
    return v;
}
__device__ __forceinline__ uint2 lds64(uint32_t a) {
    uint2 v;
    asm volatile("ld.shared.v2.b32 {%0,%1}, [%2];" : "=r"(v.x), "=r"(v.y) : "r"(a));
    return v;
}
__device__ __forceinline__ void mma16816(float* c, const uint32_t* a, const uint32_t* b) {
    asm volatile(
        "mma.sync.aligned.m16n8k16.row.col.f32.bf16.bf16.f32 "
        "{%0,%1,%2,%3}, {%4,%5,%6,%7}, {%8,%9}, {%0,%1,%2,%3};"
        : "+f"(c[0]), "+f"(c[1]), "+f"(c[2]), "+f"(c[3])
        : "r"(a[0]), "r"(a[1]), "r"(a[2]), "r"(a[3]), "r"(b[0]), "r"(b[1]));
}

// bf16x2 pack: low half = first element
__device__ __forceinline__ uint32_t bfp(float x, float y) {
    __nv_bfloat162 t = __floats2bfloat162_rn(x, y);
    return *(uint32_t*)&t;
}
__device__ __forceinline__ void split2(float2 v, uint32_t& hi, uint32_t& lo) {
    __nv_bfloat16 hx = __float2bfloat16(v.x);
    __nv_bfloat16 hy = __float2bfloat16(v.y);
    hi = (uint32_t)__bfloat16_as_ushort(hx) | ((uint32_t)__bfloat16_as_ushort(hy) << 16);
    lo = bfp(v.x - __bfloat162float(hx), v.y - __bfloat162float(hy));
}

// ---------------- pack kernels (fragment-major layout) ----------------
// A block (8KB): unit u16B = [ks(2)][mt(8)][lane(32)]; lane holds a0..a3 of
// mma m16n8k16: rows mt*16 + lane/4 (+8), k = ks*16 + (lane%4)*2 (+8)
// One unit covers 8 source floats -> nunits = elements/8
__global__ void pack_A(const float* __restrict__ src, __nv_bfloat16* __restrict__ dst,
                       int K, int nkcDst, int kcOff, size_t segstride, int nunits)
{
    int u = blockIdx.x * 256 + threadIdx.x;
    if (u >= nunits) return;
    int lane = u & 31, mt = (u >> 5) & 7, ks = (u >> 8) & 1;
    int bk = u >> 9;
    int nkcSrc = K >> 5;
    int mtile = bk / nkcSrc, kchunk = bk - mtile * nkcSrc;
    int r0 = mtile * 128 + mt * 16 + (lane >> 2);
    int kb = kchunk * 32 + ks * 16 + (lane & 3) * 2;
    const float* s0 = src + (size_t)r0 * K + kb;
    const float* s1 = s0 + (size_t)8 * K;
    uint4 hi, lo;
    split2(*(const float2*)s0,       hi.x, lo.x);   // a0
    split2(*(const float2*)s1,       hi.y, lo.y);   // a1
    split2(*(const float2*)(s0 + 8), hi.z, lo.z);   // a2
    split2(*(const float2*)(s1 + 8), hi.w, lo.w);   // a3
    size_t dblk = (size_t)mtile * nkcDst + kcOff + kchunk;
    int unit = (ks * 8 + mt) * 32 + lane;
    ((uint4*)(dst + dblk * 4096))[unit] = hi;
    ((uint4*)(dst + segstride + dblk * 4096))[unit] = lo;
}

// B block (8KB): unit u8B = [ks(2)][nt(16)][lane(32)]; lane holds b0,b1:
// n = nt*8 + lane/4, k = ks*16 + (lane%4)*2 (+8)
// One unit covers 4 source floats -> nunits = elements/4   (round-4 bug: was /8)
__global__ void pack_B(const float* __restrict__ src, __nv_bfloat16* __restrict__ dst,
                       int K, int nkcDst, size_t segstride, int nunits)
{
    int u = blockIdx.x * 256 + threadIdx.x;
    if (u >= nunits) return;
    int lane = u & 31, nt = (u >> 5) & 15, ks = (u >> 9) & 1;
    int bk = u >> 10;
    int nkcSrc = K >> 5;
    int ntile = bk / nkcSrc, kchunk = bk - ntile * nkcSrc;
    int n = ntile * 128 + nt * 8 + (lane >> 2);
    int kb = kchunk * 32 + ks * 16 + (lane & 3) * 2;
    const float* s = src + (size_t)n * K + kb;
    uint2 hi, lo;
    split2(*(const float2*)s,       hi.x, lo.x);
    split2(*(const float2*)(s + 8), hi.y, lo.y);
    size_t dblk = (size_t)ntile * nkcDst + kchunk;
    int unit = (ks * 16 + nt) * 32 + lane;
    ((uint2*)(dst + dblk * 4096))[unit] = hi;
    ((uint2*)(dst + segstride + dblk * 4096))[unit] = lo;
}

// Wcat = [w_ih | w_hh] along K (4096 cols), 8192 rows. 4 elements/unit.
__global__ void pack_Bcat(const float* __restrict__ w_ih, const float* __restrict__ w_hh,
                          __nv_bfloat16* __restrict__ dst, int nunits)
{
    int u = blockIdx.x * 256 + threadIdx.x;
    if (u >= nunits) return;
    int lane = u & 31, nt = (u >> 5) & 15, ks = (u >> 9) & 1;
    int bk = u >> 10;
    int ntile = bk >> 7, kchunk = bk & 127;   // nkcSrc = 128
    int n = ntile * 128 + nt * 8 + (lane >> 2);
    int kb = kchunk * 32 + ks * 16 + (lane & 3) * 2;
    const float* s = (kb < HID) ? (w_ih + (size_t)n * HID + kb)
                                : (w_hh + (size_t)n * HID + (kb - HID));
    uint2 hi, lo;
    split2(*(const float2*)s,       hi.x, lo.x);
    split2(*(const float2*)(s + 8), hi.y, lo.y);
    size_t dblk = (size_t)ntile * 128 + kchunk;
    int unit = (ks * 16 + nt) * 32 + lane;
    ((uint2*)(dst + dblk * 4096))[unit] = hi;
    ((uint2*)(dst + (size_t)64 * 128 * 4096 + dblk * 4096))[unit] = lo;
}

// ---------------- GEMM: C[M,N] = A * B^T, 3-pass bf16 split, mma.sync ----------------
#define NSTG 4
__global__ void __launch_bounds__(128)
gemm_mma(const __nv_bfloat16* __restrict__ Ap, const __nv_bfloat16* __restrict__ Bp,
         const float* __restrict__ bias, float* __restrict__ C,
         int nkcA, int segA, int nkcB, int segB, int kcCount, int ldc, int dotanh)
{
    extern __shared__ __align__(16) char smem[];
    const uint32_t sb = smem_u32(smem);
    const int tid = threadIdx.x;
    const int MT = blockIdx.y, NT = blockIdx.x;
    const int VK = 3 * kcCount;
    const int wid = tid >> 5, lane = tid & 31;
    const int wm = wid >> 1, wn = wid & 1;

    float acc[4][8][4];
#pragma unroll
    for (int i = 0; i < 4; i++)
#pragma unroll
        for (int j = 0; j < 8; j++)
#pragma unroll
            for (int t = 0; t < 4; t++) acc[i][j][t] = 0.0f;

    auto issue = [&](int vk) {
        int p = (vk >= 2 * kcCount) ? 2 : ((vk >= kcCount) ? 1 : 0);
        int kc = vk - p * kcCount;
        int as = (p == 2) ? segA : 0;
        int bs = (p == 1) ? segB : 0;
        const char* asrc = (const char*)(Ap + ((size_t)(as + MT * nkcA + kc)) * 4096);
        const char* bsrc = (const char*)(Bp + ((size_t)(bs + NT * nkcB + kc)) * 4096);
        uint32_t d = sb + (vk & 3) * 16384;
#pragma unroll
        for (int i = 0; i < 4; i++)
            cpasync16(d + tid * 16 + i * 2048, asrc + tid * 16 + i * 2048);
#pragma unroll
        for (int i = 0; i < 4; i++)
            cpasync16(d + 8192 + tid * 16 + i * 2048, bsrc + tid * 16 + i * 2048);
        asm volatile("cp.async.commit_group;");
    };

    issue(0); issue(1); issue(2);

    for (int vk = 0; vk < VK; vk++) {
        if (vk < VK - 2)       asm volatile("cp.async.wait_group 2;");
        else if (vk == VK - 2) asm volatile("cp.async.wait_group 1;");
        else                   asm volatile("cp.async.wait_group 0;");
        __syncthreads();
        if (vk + 3 < VK) issue(vk + 3);

        uint32_t sa = sb + (vk & 3) * 16384;
        uint32_t sbm = sa + 8192;
#pragma unroll
        for (int ks = 0; ks < 2; ks++) {
            uint32_t a[4][4], b[8][2];
#pragma unroll
            for (int i = 0; i < 4; i++) {
                uint4 v = lds128(sa + (uint32_t)((ks * 8 + wm * 4 + i) * 512 + lane * 16));
                a[i][0] = v.x; a[i][1] = v.y; a[i][2] = v.z; a[i][3] = v.w;
            }
#pragma unroll
            for (int j = 0; j < 8; j++) {
                uint2 v = lds64(sbm + (uint32_t)((ks * 16 + wn * 8 + j) * 256 + lane * 8));
                b[j][0] = v.x; b[j][1] = v.y;
            }
#pragma unroll
            for (int i = 0; i < 4; i++)
#pragma unroll
                for (int j = 0; j < 8; j++)
                    mma16816(acc[i][j], a[i], b[j]);
        }
        __syncthreads();
    }

    // epilogue
    const int rowb = MT * 128 + wm * 64;
    const int colb = NT * 128 + wn * 64;
#pragma unroll
    for (int i = 0; i < 4; i++) {
        int r0 = rowb + i * 16 + (lane >> 2);
#pragma unroll
        for (int j = 0; j < 8; j++) {
            int c0 = colb + j * 8 + (lane & 3) * 2;
            float bv0 = bias[c0], bv1 = bias[c0 + 1];
            float x0 = acc[i][j][0] + bv0, x1 = acc[i][j][1] + bv1;
            float x2 = acc[i][j][2] + bv0, x3 = acc[i][j][3] + bv1;
            if (dotanh) { x0 = tanhf(x0); x1 = tanhf(x1); x2 = tanhf(x2); x3 = tanhf(x3); }
            float2 v0 = {x0, x1}, v1 = {x2, x3};
            *(float2*)(C + (size_t)r0 * ldc + c0) = v0;
            *(float2*)(C + (size_t)(r0 + 8) * ldc + c0) = v1;
        }
    }
}

// ---------------- comm: inp = e + alive_r*(S - alive_r*h)*inv ----------------
__global__ void comm_k(const float* __restrict__ e, const float* __restrict__ h,
                       const float* __restrict__ S, const float* __restrict__ alive,
                       const float* __restrict__ nal, int do_comm, float* __restrict__ inp)
{
    int idx = blockIdx.x * 256 + threadIdx.x;
    int r = idx >> 9;
    int c = (idx & 511) << 2;
    float4 v = ((const float4*)e)[idx];
    if (do_comm) {
        float a = alive[r];
        float inv = 1.0f / (*nal - 1.0f);
        float4 hv = ((const float4*)h)[idx];
        float4 Sv = ((const float4*)S)[c >> 2];
        v.x += a * (Sv.x - a * hv.x) * inv;
        v.y += a * (Sv.y - a * hv.y) * inv;
        v.z += a * (Sv.z - a * hv.z) * inv;
        v.w += a * (Sv.w - a * hv.w) * inv;
    }
    ((float4*)inp)[idx] = v;
}

// ---------------- LSTM elementwise ----------------
__global__ void lstm_k(const float* __restrict__ z, float* __restrict__ cell,
                       float* __restrict__ h)
{
    int idx = blockIdx.x * 256 + threadIdx.x;
    int r = idx >> 9;
    int c = (idx & 511) << 2;
    const float* zr = z + (size_t)r * (4 * HID);
    float4 zi = *(const float4*)(zr + c);
    float4 zf = *(const float4*)(zr + HID + c);
    float4 zg = *(const float4*)(zr + 2 * HID + c);
    float4 zo = *(const float4*)(zr + 3 * HID + c);
    float4 cc = ((const float4*)cell)[idx];
    float4 nc, hv;
    nc.x = sigf(zf.x) * cc.x + sigf(zi.x) * tanhf(zg.x);
    nc.y = sigf(zf.y) * cc.y + sigf(zi.y) * tanhf(zg.y);
    nc.z = sigf(zf.z) * cc.z + sigf(zi.z) * tanhf(zg.z);
    nc.w = sigf(zf.w) * cc.w + sigf(zi.w) * tanhf(zg.w);
    hv.x = sigf(zo.x) * tanhf(nc.x);
    hv.y = sigf(zo.y) * tanhf(nc.y);
    hv.z = sigf(zo.z) * tanhf(nc.z);
    hv.w = sigf(zo.w) * tanhf(nc.w);
    ((float4*)cell)[idx] = nc;
    ((float4*)h)[idx] = hv;
}

// ---------------- column sums for comm ----------------
__global__ void colsum_part_k(const float* __restrict__ h, const float* __restrict__ alive,
                              float* __restrict__ part)
{
    int col = blockIdx.x * 128 + threadIdx.x;
    int r0 = blockIdx.y * 128;
    float s = 0.0f;
    for (int r = r0; r < r0 + 128; r++)
        s = fmaf(alive[r], h[(size_t)r * HID + col], s);
    part[blockIdx.y * HID + col] = s;
}
__global__ void colsum_red_k(const float* __restrict__ part, float* __restrict__ S)
{
    int c = blockIdx.x * 256 + threadIdx.x;
    float s = 0.0f;
#pragma unroll
    for (int i = 0; i < 16; i++) s += part[i * HID + c];
    S[c] = s;
}

// ---------------- misc ----------------
__global__ void nalive_k(const float* __restrict__ alive, float* __restrict__ out, int n)
{
    __shared__ float s[256];
    float v = 0.0f;
    for (int i = threadIdx.x; i < n; i += 256) v += alive[i];
    s[threadIdx.x] = v;
    __syncthreads();
    for (int st = 128; st > 0; st >>= 1) {
        if (threadIdx.x < st) s[threadIdx.x] += s[threadIdx.x + st];
        __syncthreads();
    }
    if (threadIdx.x == 0) *out = s[0];
}
__global__ void bias_sum_k(const float* __restrict__ a, const float* __restrict__ b,
                           float* __restrict__ o, int n)
{
    int i = blockIdx.x * blockDim.x + threadIdx.x;
    if (i < n) o[i] = a[i] + b[i];
}

// ---------------- head ----------------
__global__ void __launch_bounds__(256)
head_k(const float* __restrict__ h,
       const float* __restrict__ act_w, const float* __restrict__ act_b,
       const float* __restrict__ val_w, const float* __restrict__ val_b,
       float* __restrict__ out)
{
    const int n = blockIdx.x;
    const int tid = threadIdx.x;
    __shared__ float sh[HID];
    __shared__ float partial[4][ACT_D];
    __shared__ float vred[256];
    __shared__ float logits[ACT_D];

    const float* hr = h + (size_t)n * HID;
    for (int k = tid; k < HID; k += 256) sh[k] = hr[k];
    __syncthreads();

    const int col = tid & 63;
    const int part = tid >> 6;
    const float* w = act_w + (size_t)col * HID;
    float s = 0.0f;
    const int kbeg = part * (HID / 4);
    for (int k = kbeg; k < kbeg + HID / 4; k++) s = fmaf(sh[k], w[k], s);
    partial[part][col] = s;

    float v = 0.0f;
    for (int k = tid; k < HID; k += 256) v = fmaf(sh[k], val_w[k], v);
    vred[tid] = v;
    __syncthreads();

    if (tid < ACT_D)
        logits[tid] = partial[0][tid] + partial[1][tid] + partial[2][tid]
                    + partial[3][tid] + act_b[tid];

    for (int st = 128; st > 0; st >>= 1) {
        if (tid < st) vred[tid] += vred[tid + st];
        __syncthreads();
    }
    if (tid == 0) out[(size_t)NN_AG * ACT_D + n] = vred[0] + val_b[0];

    if (tid < 32) {
        float a = logits[tid], b = logits[tid + 32];
        float m = fmaxf(a, b);
#pragma unroll
        for (int o = 16; o > 0; o >>= 1) m = fmaxf(m, __shfl_xor_sync(0xffffffffu, m, o));
        float se = expf(a - m) + expf(b - m);
#pragma unroll
        for (int o = 16; o > 0; o >>= 1) se += __shfl_xor_sync(0xffffffffu, se, o);
        float lse = m + logf(se);
        out[(size_t)n * ACT_D + tid]      = a - lse;
        out[(size_t)n * ACT_D + tid + 32] = b - lse;
    }
}

// ---------------- launcher ----------------
extern "C" void kernel_launch(void* const* d_in, const int* in_sizes, int n_in,
                              void* d_out, int out_size)
{
    const float* obs    = (const float*)d_in[0];
    const float* alive  = (const float*)d_in[1];
    const float* enc_w  = (const float*)d_in[2];
    const float* enc_b  = (const float*)d_in[3];
    // d_in[4], d_in[5]: g_w, g_b — gate == 1 always (ceil(sigmoid) with |logit| << 104)
    const float* w_ih   = (const float*)d_in[6];
    const float* w_hh   = (const float*)d_in[7];
    const float* b_ih   = (const float*)d_in[8];
    const float* b_hh   = (const float*)d_in[9];
    const float* act_w  = (const float*)d_in[10];
    const float* act_b  = (const float*)d_in[11];
    const float* val_w  = (const float*)d_in[12];
    const float* val_b  = (const float*)d_in[13];
    float* out = (float*)d_out;

    float *e, *h, *cell, *inp, *z, *part, *S, *bsum, *nal;
    __nv_bfloat16 *Apack, *Aobs, *Wcat, *Wenc;
    cudaGetSymbolAddress((void**)&e,     g_e);
    cudaGetSymbolAddress((void**)&h,     g_h);
    cudaGetSymbolAddress((void**)&cell,  g_cell);
    cudaGetSymbolAddress((void**)&inp,   g_inp);
    cudaGetSymbolAddress((void**)&z,     g_z);
    cudaGetSymbolAddress((void**)&part,  g_part);
    cudaGetSymbolAddress((void**)&S,     g_S);
    cudaGetSymbolAddress((void**)&bsum,  g_bsum);
    cudaGetSymbolAddress((void**)&nal,   g_nalive);
    cudaGetSymbolAddress((void**)&Apack, g_Apack);
    cudaGetSymbolAddress((void**)&Aobs,  g_Aobs);
    cudaGetSymbolAddress((void**)&Wcat,  g_Wcat);
    cudaGetSymbolAddress((void**)&Wenc,  g_Wenc);

    cudaFuncSetAttribute(gemm_mma, cudaFuncAttributeMaxDynamicSharedMemorySize,
                         NSTG * 16384);

    const size_t NH = (size_t)NN_AG * HID;
    cudaMemsetAsync(h,    0, NH * sizeof(float));
    cudaMemsetAsync(cell, 0, NH * sizeof(float));

    nalive_k<<<1, 256>>>(alive, nal, NN_AG);
    bias_sum_k<<<(4 * HID + 255) / 256, 256>>>(b_ih, b_hh, bsum, 4 * HID);

    // weight/obs packs (pack_A: 8 elems/unit; pack_B/pack_Bcat: 4 elems/unit)
    {
        int unitsAobs = NN_AG * OBS_D / 8;
        pack_A<<<(unitsAobs + 255) / 256, 256>>>(
            obs, Aobs, OBS_D, 32, 0, (size_t)16 * 32 * 4096, unitsAobs);
        int unitsWenc = HID * OBS_D / 4;
        pack_B<<<(unitsWenc + 255) / 256, 256>>>(
            enc_w, Wenc, OBS_D, 32, (size_t)16 * 32 * 4096, unitsWenc);
        int unitsWcat = (4 * HID) * (2 * HID) / 4;
        pack_Bcat<<<(unitsWcat + 255) / 256, 256>>>(w_ih, w_hh, Wcat, unitsWcat);
    }

    // encoder: e = tanh(obs @ enc_w^T + enc_b)
    {
        dim3 grid(HID / 128, NN_AG / 128);
        gemm_mma<<<grid, 128, NSTG * 16384>>>(Aobs, Wenc, enc_b, e,
                                              32, 16 * 32, 32, 16 * 32, 32, HID, 1);
    }

    const int np4 = (int)(NH / 4);
    const dim3 gridZ(4 * HID / 128, NN_AG / 128);
    const dim3 gridCS(HID / 128, 16);
    const int nunitsA = (int)(NH / 8);

    for (int it = 0; it < ITERS; it++) {
        if (it > 0) {
            colsum_part_k<<<gridCS, 128>>>(h, alive, part);
            colsum_red_k<<<HID / 256, 256>>>(part, S);
        }
        comm_k<<<np4 / 256, 256>>>(e, h, S, alive, nal, it > 0 ? 1 : 0, inp);
        pack_A<<<(nunitsA + 255) / 256, 256>>>(
            inp, Apack, HID, 128, 0, (size_t)16 * 128 * 4096, nunitsA);
        // z = [inp|h] @ [w_ih|w_hh]^T + bsum  (iter 0: h == 0 exactly -> half K)
        gemm_mma<<<gridZ, 128, NSTG * 16384>>>(Apack, Wcat, bsum, z,
                                               128, 16 * 128, 128, 64 * 128,
                                               (it > 0) ? 128 : 64, 4 * HID, 0);
        lstm_k<<<np4 / 256, 256>>>(z, cell, h);
        if (it < ITERS - 1) {
            pack_A<<<(nunitsA + 255) / 256, 256>>>(
                h, Apack, HID, 128, 64, (size_t)16 * 128 * 4096, nunitsA);
        }
    }

    head_k<<<NN_AG, 256>>>(h, act_w, act_b, val_w, val_b, out);
}

// round 7
// speedup vs baseline: 3.7115x; 1.0459x over previous
#include <cuda_runtime.h>
#include <cuda_bf16.h>
#include <math.h>
#include <stdint.h>

// ---------------- problem constants ----------------
#define NN_AG 2048
#define HID   2048
#define OBS_D 1024
#define ACT_D 64
#define ITERS 3

// ---------------- device scratch ----------------
// fragment-major packed bf16 operands; one 8KB block = 128 rows x 32 k
__device__ __align__(16) __nv_bfloat16 g_Apack[(size_t)2 * 16 * 128 * 4096]; // [inp|h]
__device__ __align__(16) __nv_bfloat16 g_Aobs [(size_t)2 * 16 * 32  * 4096];
__device__ __align__(16) __nv_bfloat16 g_Wcat [(size_t)2 * 64 * 128 * 4096]; // [w_ih|w_hh]
__device__ __align__(16) __nv_bfloat16 g_Wenc [(size_t)2 * 16 * 32  * 4096];
__device__ float g_e   [(size_t)NN_AG * HID];
__device__ float g_h   [(size_t)NN_AG * HID];
__device__ float g_cell[(size_t)NN_AG * HID];
__device__ float g_inp [(size_t)NN_AG * HID];
__device__ float g_z   [(size_t)NN_AG * 4 * HID];
__device__ float g_part[16 * HID];
__device__ float g_S   [HID];
__device__ float g_bsum[4 * HID];
__device__ float g_nalive;

#define APACK_SEG ((size_t)16 * 128 * 4096)   // elements
#define WCAT_SEG  ((size_t)64 * 128 * 4096)
#define AOBS_SEG  ((size_t)16 * 32 * 4096)

__device__ __forceinline__ float sigf(float x) { return 1.0f / (1.0f + expf(-x)); }

// ---------------- low-level helpers ----------------
__device__ __forceinline__ uint32_t smem_u32(const void* p) {
    uint32_t a;
    asm("{ .reg .u64 t; cvta.to.shared.u64 t, %1; cvt.u32.u64 %0, t; }" : "=r"(a) : "l"(p));
    return a;
}
__device__ __forceinline__ void cpasync16(uint32_t d, const void* s) {
    asm volatile("cp.async.cg.shared.global [%0], [%1], 16;" :: "r"(d), "l"(s));
}
__device__ __forceinline__ uint4 lds128(uint32_t a) {
    uint4 v;
    asm volatile("ld.shared.v4.b32 {%0,%1,%2,%3}, [%4];"
                 : "=r"(v.x), "=r"(v.y), "=r"(v.z), "=r"(v.w) : "r"(a));
    return v;
}
__device__ __forceinline__ uint2 lds64(uint32_t a) {
    uint2 v;
    asm volatile("ld.shared.v2.b32 {%0,%1}, [%2];" : "=r"(v.x), "=r"(v.y) : "r"(a));
    return v;
}
__device__ __forceinline__ void mma16816(float* c, const uint32_t* a, const uint32_t* b) {
    asm volatile(
        "mma.sync.aligned.m16n8k16.row.col.f32.bf16.bf16.f32 "
        "{%0,%1,%2,%3}, {%4,%5,%6,%7}, {%8,%9}, {%0,%1,%2,%3};"
        : "+f"(c[0]), "+f"(c[1]), "+f"(c[2]), "+f"(c[3])
        : "r"(a[0]), "r"(a[1]), "r"(a[2]), "r"(a[3]), "r"(b[0]), "r"(b[1]));
}
__device__ __forceinline__ uint32_t bfp(float x, float y) {
    __nv_bfloat162 t = __floats2bfloat162_rn(x, y);
    return *(uint32_t*)&t;
}
__device__ __forceinline__ void split2(float2 v, uint32_t& hi, uint32_t& lo) {
    __nv_bfloat16 hx = __float2bfloat16(v.x);
    __nv_bfloat16 hy = __float2bfloat16(v.y);
    hi = (uint32_t)__bfloat16_as_ushort(hx) | ((uint32_t)__bfloat16_as_ushort(hy) << 16);
    lo = bfp(v.x - __bfloat162float(hx), v.y - __bfloat162float(hy));
}

// ---------------- pack kernels (fragment-major, identical to round 5) ----------------
__global__ void pack_A(const float* __restrict__ src, __nv_bfloat16* __restrict__ dst,
                       int K, int nkcDst, int kcOff, size_t segstride, int nunits)
{
    int u = blockIdx.x * 256 + threadIdx.x;
    if (u >= nunits) return;
    int lane = u & 31, mt = (u >> 5) & 7, ks = (u >> 8) & 1;
    int bk = u >> 9;
    int nkcSrc = K >> 5;
    int mtile = bk / nkcSrc, kchunk = bk - mtile * nkcSrc;
    int r0 = mtile * 128 + mt * 16 + (lane >> 2);
    int kb = kchunk * 32 + ks * 16 + (lane & 3) * 2;
    const float* s0 = src + (size_t)r0 * K + kb;
    const float* s1 = s0 + (size_t)8 * K;
    uint4 hi, lo;
    split2(*(const float2*)s0,       hi.x, lo.x);
    split2(*(const float2*)s1,       hi.y, lo.y);
    split2(*(const float2*)(s0 + 8), hi.z, lo.z);
    split2(*(const float2*)(s1 + 8), hi.w, lo.w);
    size_t dblk = (size_t)mtile * nkcDst + kcOff + kchunk;
    int unit = (ks * 8 + mt) * 32 + lane;
    ((uint4*)(dst + dblk * 4096))[unit] = hi;
    ((uint4*)(dst + segstride + dblk * 4096))[unit] = lo;
}

__global__ void pack_B(const float* __restrict__ src, __nv_bfloat16* __restrict__ dst,
                       int K, int nkcDst, size_t segstride, int nunits)
{
    int u = blockIdx.x * 256 + threadIdx.x;
    if (u >= nunits) return;
    int lane = u & 31, nt = (u >> 5) & 15, ks = (u >> 9) & 1;
    int bk = u >> 10;
    int nkcSrc = K >> 5;
    int ntile = bk / nkcSrc, kchunk = bk - ntile * nkcSrc;
    int n = ntile * 128 + nt * 8 + (lane >> 2);
    int kb = kchunk * 32 + ks * 16 + (lane & 3) * 2;
    const float* s = src + (size_t)n * K + kb;
    uint2 hi, lo;
    split2(*(const float2*)s,       hi.x, lo.x);
    split2(*(const float2*)(s + 8), hi.y, lo.y);
    size_t dblk = (size_t)ntile * nkcDst + kchunk;
    int unit = (ks * 16 + nt) * 32 + lane;
    ((uint2*)(dst + dblk * 4096))[unit] = hi;
    ((uint2*)(dst + segstride + dblk * 4096))[unit] = lo;
}

// Wcat = [w_ih | w_hh] along K (4096 cols), 8192 rows, NO gate permutation
__global__ void pack_Bcat(const float* __restrict__ w_ih, const float* __restrict__ w_hh,
                          __nv_bfloat16* __restrict__ dst, int nunits)
{
    int u = blockIdx.x * 256 + threadIdx.x;
    if (u >= nunits) return;
    int lane = u & 31, nt = (u >> 5) & 15, ks = (u >> 9) & 1;
    int bk = u >> 10;
    int ntile = bk >> 7, kchunk = bk & 127;
    int n = ntile * 128 + nt * 8 + (lane >> 2);
    int kb = kchunk * 32 + ks * 16 + (lane & 3) * 2;
    const float* s = (kb < HID) ? (w_ih + (size_t)n * HID + kb)
                                : (w_hh + (size_t)n * HID + (kb - HID));
    uint2 hi, lo;
    split2(*(const float2*)s,       hi.x, lo.x);
    split2(*(const float2*)(s + 8), hi.y, lo.y);
    size_t dblk = (size_t)ntile * 128 + kchunk;
    int unit = (ks * 16 + nt) * 32 + lane;
    ((uint2*)(dst + dblk * 4096))[unit] = hi;
    ((uint2*)(dst + WCAT_SEG + dblk * 4096))[unit] = lo;
}

// ---------------- fused GEMM: C = A*B^T, 3 mma-passes per resident chunk ----------------
// stage = 32KB: [A_hi 8K][A_lo 8K][B_hi 8K][B_lo 8K]; 3 stages.
template<int ACT>
__global__ void __launch_bounds__(128, 2)
gemm_fused(const __nv_bfloat16* __restrict__ Ap, const __nv_bfloat16* __restrict__ Bp,
           const float* __restrict__ bias, float* __restrict__ C,
           size_t segAB, size_t segBB,   // BYTE offsets hi->lo segment
           int nkcA, int nkcB, int kcCount, int ldc)
{
    extern __shared__ __align__(16) char smem[];   // 3 * 32768
    const uint32_t sb = smem_u32(smem);
    const int tid = threadIdx.x;
    const int MT = blockIdx.y, NT = blockIdx.x;
    const int wid = tid >> 5, lane = tid & 31;
    const int wm = wid >> 1, wn = wid & 1;

    float acc[4][8][4];
#pragma unroll
    for (int i = 0; i < 4; i++)
#pragma unroll
        for (int j = 0; j < 8; j++)
#pragma unroll
            for (int t = 0; t < 4; t++) acc[i][j][t] = 0.0f;

    auto issue = [&](int c) {
        const char* ab = (const char*)Ap + ((size_t)MT * nkcA + c) * 8192;
        const char* bb = (const char*)Bp + ((size_t)NT * nkcB + c) * 8192;
        uint32_t d = sb + (uint32_t)(c % 3) * 32768u;
#pragma unroll
        for (int i = 0; i < 4; i++) {
            uint32_t o = i * 2048 + tid * 16;
            cpasync16(d + o,         ab + o);
            cpasync16(d + 8192 + o,  ab + segAB + o);
            cpasync16(d + 16384 + o, bb + o);
            cpasync16(d + 24576 + o, bb + segBB + o);
        }
        asm volatile("cp.async.commit_group;");
    };

    issue(0);
    issue(1);

    for (int vk = 0; vk < kcCount; vk++) {
        if (vk + 1 < kcCount) asm volatile("cp.async.wait_group 1;");
        else                  asm volatile("cp.async.wait_group 0;");
        __syncthreads();
        if (vk + 2 < kcCount) issue(vk + 2);

        uint32_t st = sb + (uint32_t)(vk % 3) * 32768u;
#pragma unroll
        for (int ks = 0; ks < 2; ks++) {
            uint32_t ah[4][4], al[4][4], b[8][2];
#pragma unroll
            for (int i = 0; i < 4; i++) {
                uint4 v = lds128(st + (uint32_t)((ks * 8 + wm * 4 + i) * 512 + lane * 16));
                ah[i][0] = v.x; ah[i][1] = v.y; ah[i][2] = v.z; ah[i][3] = v.w;
            }
#pragma unroll
            for (int j = 0; j < 8; j++) {
                uint2 v = lds64(st + 16384u + (uint32_t)((ks * 16 + wn * 8 + j) * 256 + lane * 8));
                b[j][0] = v.x; b[j][1] = v.y;
            }
#pragma unroll
            for (int i = 0; i < 4; i++)
#pragma unroll
                for (int j = 0; j < 8; j++) mma16816(acc[i][j], ah[i], b[j]);   // hi*hi
#pragma unroll
            for (int i = 0; i < 4; i++) {
                uint4 v = lds128(st + 8192u + (uint32_t)((ks * 8 + wm * 4 + i) * 512 + lane * 16));
                al[i][0] = v.x; al[i][1] = v.y; al[i][2] = v.z; al[i][3] = v.w;
            }
#pragma unroll
            for (int i = 0; i < 4; i++)
#pragma unroll
                for (int j = 0; j < 8; j++) mma16816(acc[i][j], al[i], b[j]);   // lo*hi
#pragma unroll
            for (int j = 0; j < 8; j++) {
                uint2 v = lds64(st + 24576u + (uint32_t)((ks * 16 + wn * 8 + j) * 256 + lane * 8));
                b[j][0] = v.x; b[j][1] = v.y;
            }
#pragma unroll
            for (int i = 0; i < 4; i++)
#pragma unroll
                for (int j = 0; j < 8; j++) mma16816(acc[i][j], ah[i], b[j]);   // hi*lo
        }
        __syncthreads();
    }

    // epilogue (round-5 style)
    const int rowb = MT * 128 + wm * 64;
    const int colb = NT * 128 + wn * 64;
#pragma unroll
    for (int i = 0; i < 4; i++) {
        int r0 = rowb + i * 16 + (lane >> 2);
#pragma unroll
        for (int j = 0; j < 8; j++) {
            int c0 = colb + j * 8 + (lane & 3) * 2;
            float b0 = bias[c0], b1 = bias[c0 + 1];
            float x0 = acc[i][j][0] + b0, x1 = acc[i][j][1] + b1;
            float x2 = acc[i][j][2] + b0, x3 = acc[i][j][3] + b1;
            if (ACT == 1) { x0 = tanhf(x0); x1 = tanhf(x1); x2 = tanhf(x2); x3 = tanhf(x3); }
            float2 v0 = {x0, x1}, v1 = {x2, x3};
            *(float2*)(C + (size_t)r0 * ldc + c0) = v0;
            *(float2*)(C + (size_t)(r0 + 8) * ldc + c0) = v1;
        }
    }
}

// ---------------- comm: inp = e + alive_r*(S - alive_r*h)*inv ----------------
__global__ void comm_k(const float* __restrict__ e, const float* __restrict__ h,
                       const float* __restrict__ S, const float* __restrict__ alive,
                       const float* __restrict__ nal, int do_comm, float* __restrict__ inp)
{
    int idx = blockIdx.x * 256 + threadIdx.x;
    int r = idx >> 9;
    int c = (idx & 511) << 2;
    float4 v = ((const float4*)e)[idx];
    if (do_comm) {
        float a = alive[r];
        float inv = 1.0f / (*nal - 1.0f);
        float4 hv = ((const float4*)h)[idx];
        float4 Sv = ((const float4*)S)[c >> 2];
        v.x += a * (Sv.x - a * hv.x) * inv;
        v.y += a * (Sv.y - a * hv.y) * inv;
        v.z += a * (Sv.z - a * hv.z) * inv;
        v.w += a * (Sv.w - a * hv.w) * inv;
    }
    ((float4*)inp)[idx] = v;
}

// ---------------- LSTM elementwise ----------------
__global__ void lstm_k(const float* __restrict__ z, float* __restrict__ cell,
                       float* __restrict__ h)
{
    int idx = blockIdx.x * 256 + threadIdx.x;
    int r = idx >> 9;
    int c = (idx & 511) << 2;
    const float* zr = z + (size_t)r * (4 * HID);
    float4 zi = *(const float4*)(zr + c);
    float4 zf = *(const float4*)(zr + HID + c);
    float4 zg = *(const float4*)(zr + 2 * HID + c);
    float4 zo = *(const float4*)(zr + 3 * HID + c);
    float4 cc = ((const float4*)cell)[idx];
    float4 nc, hv;
    nc.x = sigf(zf.x) * cc.x + sigf(zi.x) * tanhf(zg.x);
    nc.y = sigf(zf.y) * cc.y + sigf(zi.y) * tanhf(zg.y);
    nc.z = sigf(zf.z) * cc.z + sigf(zi.z) * tanhf(zg.z);
    nc.w = sigf(zf.w) * cc.w + sigf(zi.w) * tanhf(zg.w);
    hv.x = sigf(zo.x) * tanhf(nc.x);
    hv.y = sigf(zo.y) * tanhf(nc.y);
    hv.z = sigf(zo.z) * tanhf(nc.z);
    hv.w = sigf(zo.w) * tanhf(nc.w);
    ((float4*)cell)[idx] = nc;
    ((float4*)h)[idx] = hv;
}

// ---------------- column sums for comm ----------------
__global__ void colsum_part_k(const float* __restrict__ h, const float* __restrict__ alive,
                              float* __restrict__ part)
{
    int col = blockIdx.x * 128 + threadIdx.x;
    int r0 = blockIdx.y * 128;
    float s = 0.0f;
    for (int r = r0; r < r0 + 128; r++)
        s = fmaf(alive[r], h[(size_t)r * HID + col], s);
    part[blockIdx.y * HID + col] = s;
}
__global__ void colsum_red_k(const float* __restrict__ part, float* __restrict__ S)
{
    int c = blockIdx.x * 256 + threadIdx.x;
    float s = 0.0f;
#pragma unroll
    for (int i = 0; i < 16; i++) s += part[i * HID + c];
    S[c] = s;
}

// ---------------- misc ----------------
__global__ void nalive_k(const float* __restrict__ alive, float* __restrict__ out, int n)
{
    __shared__ float s[256];
    float v = 0.0f;
    for (int i = threadIdx.x; i < n; i += 256) v += alive[i];
    s[threadIdx.x] = v;
    __syncthreads();
    for (int st = 128; st > 0; st >>= 1) {
        if (threadIdx.x < st) s[threadIdx.x] += s[threadIdx.x + st];
        __syncthreads();
    }
    if (threadIdx.x == 0) *out = s[0];
}
__global__ void bias_sum_k(const float* __restrict__ a, const float* __restrict__ b,
                           float* __restrict__ o, int n)
{
    int i = blockIdx.x * blockDim.x + threadIdx.x;
    if (i < n) o[i] = a[i] + b[i];
}

// ---------------- head ----------------
__global__ void __launch_bounds__(256)
head_k(const float* __restrict__ h,
       const float* __restrict__ act_w, const float* __restrict__ act_b,
       const float* __restrict__ val_w, const float* __restrict__ val_b,
       float* __restrict__ out)
{
    const int n = blockIdx.x;
    const int tid = threadIdx.x;
    __shared__ float sh[HID];
    __shared__ float partial[4][ACT_D];
    __shared__ float vred[256];
    __shared__ float logits[ACT_D];

    const float* hr = h + (size_t)n * HID;
    for (int k = tid; k < HID; k += 256) sh[k] = hr[k];
    __syncthreads();

    const int col = tid & 63;
    const int part = tid >> 6;
    const float* w = act_w + (size_t)col * HID;
    float s = 0.0f;
    const int kbeg = part * (HID / 4);
    for (int k = kbeg; k < kbeg + HID / 4; k++) s = fmaf(sh[k], w[k], s);
    partial[part][col] = s;

    float v = 0.0f;
    for (int k = tid; k < HID; k += 256) v = fmaf(sh[k], val_w[k], v);
    vred[tid] = v;
    __syncthreads();

    if (tid < ACT_D)
        logits[tid] = partial[0][tid] + partial[1][tid] + partial[2][tid]
                    + partial[3][tid] + act_b[tid];

    for (int st = 128; st > 0; st >>= 1) {
        if (tid < st) vred[tid] += vred[tid + st];
        __syncthreads();
    }
    if (tid == 0) out[(size_t)NN_AG * ACT_D + n] = vred[0] + val_b[0];

    if (tid < 32) {
        float a = logits[tid], b = logits[tid + 32];
        float m = fmaxf(a, b);
#pragma unroll
        for (int o = 16; o > 0; o >>= 1) m = fmaxf(m, __shfl_xor_sync(0xffffffffu, m, o));
        float se = expf(a - m) + expf(b - m);
#pragma unroll
        for (int o = 16; o > 0; o >>= 1) se += __shfl_xor_sync(0xffffffffu, se, o);
        float lse = m + logf(se);
        out[(size_t)n * ACT_D + tid]      = a - lse;
        out[(size_t)n * ACT_D + tid + 32] = b - lse;
    }
}

// ---------------- launcher ----------------
extern "C" void kernel_launch(void* const* d_in, const int* in_sizes, int n_in,
                              void* d_out, int out_size)
{
    const float* obs    = (const float*)d_in[0];
    const float* alive  = (const float*)d_in[1];
    const float* enc_w  = (const float*)d_in[2];
    const float* enc_b  = (const float*)d_in[3];
    // d_in[4], d_in[5]: g_w, g_b — gate == 1 always (ceil(sigmoid), |logit| << 104)
    const float* w_ih   = (const float*)d_in[6];
    const float* w_hh   = (const float*)d_in[7];
    const float* b_ih   = (const float*)d_in[8];
    const float* b_hh   = (const float*)d_in[9];
    const float* act_w  = (const float*)d_in[10];
    const float* act_b  = (const float*)d_in[11];
    const float* val_w  = (const float*)d_in[12];
    const float* val_b  = (const float*)d_in[13];
    float* out = (float*)d_out;

    float *e, *h, *cell, *inp, *z, *part, *S, *bsum, *nal;
    __nv_bfloat16 *Apack, *Aobs, *Wcat, *Wenc;
    cudaGetSymbolAddress((void**)&e,     g_e);
    cudaGetSymbolAddress((void**)&h,     g_h);
    cudaGetSymbolAddress((void**)&cell,  g_cell);
    cudaGetSymbolAddress((void**)&inp,   g_inp);
    cudaGetSymbolAddress((void**)&z,     g_z);
    cudaGetSymbolAddress((void**)&part,  g_part);
    cudaGetSymbolAddress((void**)&S,     g_S);
    cudaGetSymbolAddress((void**)&bsum,  g_bsum);
    cudaGetSymbolAddress((void**)&nal,   g_nalive);
    cudaGetSymbolAddress((void**)&Apack, g_Apack);
    cudaGetSymbolAddress((void**)&Aobs,  g_Aobs);
    cudaGetSymbolAddress((void**)&Wcat,  g_Wcat);
    cudaGetSymbolAddress((void**)&Wenc,  g_Wenc);

    cudaFuncSetAttribute(gemm_fused<0>, cudaFuncAttributeMaxDynamicSharedMemorySize, 3 * 32768);
    cudaFuncSetAttribute(gemm_fused<1>, cudaFuncAttributeMaxDynamicSharedMemorySize, 3 * 32768);

    const size_t NH = (size_t)NN_AG * HID;
    cudaMemsetAsync(h,    0, NH * sizeof(float));
    cudaMemsetAsync(cell, 0, NH * sizeof(float));

    nalive_k<<<1, 256>>>(alive, nal, NN_AG);
    bias_sum_k<<<(4 * HID + 255) / 256, 256>>>(b_ih, b_hh, bsum, 4 * HID);

    // operand packs
    {
        int unitsAobs = NN_AG * OBS_D / 8;
        pack_A<<<(unitsAobs + 255) / 256, 256>>>(obs, Aobs, OBS_D, 32, 0, AOBS_SEG, unitsAobs);
        int unitsWenc = HID * OBS_D / 4;
        pack_B<<<(unitsWenc + 255) / 256, 256>>>(enc_w, Wenc, OBS_D, 32, AOBS_SEG, unitsWenc);
        int unitsWcat = (4 * HID) * (2 * HID) / 4;
        pack_Bcat<<<(unitsWcat + 255) / 256, 256>>>(w_ih, w_hh, Wcat, unitsWcat);
    }

    // encoder: e = tanh(obs @ enc_w^T + enc_b)
    {
        dim3 grid(HID / 128, NN_AG / 128);
        gemm_fused<1><<<grid, 128, 3 * 32768>>>(Aobs, Wenc, enc_b, e,
                                                AOBS_SEG * 2, AOBS_SEG * 2,
                                                32, 32, 32, HID);
    }

    const int np4 = (int)(NH / 4);
    const dim3 gridZ(4 * HID / 128, NN_AG / 128);
    const dim3 gridCS(HID / 128, 16);
    const int nunitsA = (int)(NH / 8);

    for (int it = 0; it < ITERS; it++) {
        if (it > 0) {
            colsum_part_k<<<gridCS, 128>>>(h, alive, part);
            colsum_red_k<<<HID / 256, 256>>>(part, S);
        }
        comm_k<<<np4 / 256, 256>>>(e, h, S, alive, nal, it > 0 ? 1 : 0, inp);
        pack_A<<<(nunitsA + 255) / 256, 256>>>(
            inp, Apack, HID, 128, 0, APACK_SEG, nunitsA);
        // z = [inp|h] @ Wcat^T + bsum  (iter 0: h == 0 exactly -> half K)
        gemm_fused<0><<<gridZ, 128, 3 * 32768>>>(Apack, Wcat, bsum, z,
                                                 APACK_SEG * 2, WCAT_SEG * 2,
                                                 128, 128, (it > 0) ? 128 : 64, 4 * HID);
        lstm_k<<<np4 / 256, 256>>>(z, cell, h);
        if (it < ITERS - 1) {
            pack_A<<<(nunitsA + 255) / 256, 256>>>(
                h, Apack, HID, 128, 64, APACK_SEG, nunitsA);
        }
    }

    head_k<<<NN_AG, 256>>>(h, act_w, act_b, val_w, val_b, out);
}